// round 2
// baseline (speedup 1.0000x reference)
#include <cuda_runtime.h>
#include <stdint.h>

// Banded outer product: out[b,i,j] = s[b,i]*e[b,j] for 0 <= j-i <= 15, else 0.
// B=16, L=4096. Output 1.073 GB fp32 -> pure HBM-store-bound (R1: DRAM=85.9%).
//
// R2: persistent one-wave grid-stride (148 SMs x 8 blocks), each block loops
// over ~55 rows; removes ~55 wave transitions + per-block prologue overhead.
// Chunk-level band test (float4-index range) instead of per-element gating.

#define LDIM  4096
#define BAND  15
#define NROWS (16 * LDIM)

__global__ __launch_bounds__(256, 8)
void band_outer_kernel(const float* __restrict__ s,
                       const float* __restrict__ e,
                       float* __restrict__ out)
{
    const int t = threadIdx.x;

    for (int row = blockIdx.x; row < NROWS; row += gridDim.x) {
        const int i  = row & (LDIM - 1);
        const float sv = s[row];
        const float* __restrict__ erow = e + (row & ~(LDIM - 1));
        float4* __restrict__ orow =
            reinterpret_cast<float4*>(out) + (size_t)row * (LDIM / 4);

        const int lo4 = i >> 2;             // first float4 chunk touching band
        const int hi4 = (i + BAND) >> 2;    // last  float4 chunk touching band

#pragma unroll
        for (int k = 0; k < 4; ++k) {
            const int c4 = t + k * 256;     // float4 index within the row
            float4 v = make_float4(0.f, 0.f, 0.f, 0.f);

            if (c4 >= lo4 && c4 <= hi4) {
                const int j = c4 << 2;
                if (j     >= i && j     <= i + BAND) v.x = sv * erow[j];
                if (j + 1 >= i && j + 1 <= i + BAND) v.y = sv * erow[j + 1];
                if (j + 2 >= i && j + 2 <= i + BAND) v.z = sv * erow[j + 2];
                if (j + 3 >= i && j + 3 <= i + BAND) v.w = sv * erow[j + 3];
            }
            // streaming store: write-once output, keep out of L2 residency
            __stcs(&orow[c4], v);
        }
    }
}

extern "C" void kernel_launch(void* const* d_in, const int* in_sizes, int n_in,
                              void* d_out, int out_size)
{
    const float* s = (const float*)d_in[0];
    const float* e = (const float*)d_in[1];
    float* out = (float*)d_out;

    // one wave: 148 SMs x 8 resident blocks
    band_outer_kernel<<<148 * 8, 256>>>(s, e, out);
}

// round 5
// speedup vs baseline: 1.2248x; 1.2248x over previous
#include <cuda_runtime.h>
#include <stdint.h>

// Banded outer product: out[b,i,j] = s[b,i]*e[b,j] for 0 <= j-i <= 15, else 0.
// B=16, L=4096. Output 1.073 GB fp32 -> pure HBM-store-bound.
//
// R5 = R3/R4 resubmit (both benches were broker infra failures, no data).
// One block per output row. Phase 1: unconditional zero-fill of all 1024
// float4 chunks (dependency-free store stream). Phase 2: overwrite the <=5
// band-intersecting chunks; same owning thread + same address -> program
// order guarantees the final value. ~0.5% duplicate traffic.

#define LDIM 4096
#define BAND 15

__global__ __launch_bounds__(256, 8)
void band_outer_kernel(const float* __restrict__ s,
                       const float* __restrict__ e,
                       float* __restrict__ out)
{
    const int row = blockIdx.x;          // b*L + i
    const int i   = row & (LDIM - 1);
    const int t   = threadIdx.x;

    // issue the broadcast load early; latency hides under the zero stores
    const float sv = __ldg(&s[row]);
    const float* __restrict__ erow = e + (row & ~(LDIM - 1));

    float4* __restrict__ orow =
        reinterpret_cast<float4*>(out) + (size_t)row * (LDIM / 4);

    // ---- phase 1: unconditional zero fill (dependency-free store stream) ----
    const float4 z = make_float4(0.f, 0.f, 0.f, 0.f);
#pragma unroll
    for (int k = 0; k < 4; ++k) {
        __stcs(&orow[t + k * 256], z);
    }

    // ---- phase 2: overwrite the band chunks (<=5 per row) ----
    const int lo4 = i >> 2;
    const int hi4 = (i + BAND) >> 2;    // c4 <= 1023 always, j < LDIM holds

#pragma unroll
    for (int k = 0; k < 4; ++k) {
        const int c4 = t + k * 256;
        if (c4 >= lo4 && c4 <= hi4) {
            const int j = c4 << 2;
            float4 v;
            v.x = ((unsigned)(j     - i) <= BAND) ? sv * __ldg(&erow[j])     : 0.f;
            v.y = ((unsigned)(j + 1 - i) <= BAND) ? sv * __ldg(&erow[j + 1]) : 0.f;
            v.z = ((unsigned)(j + 2 - i) <= BAND) ? sv * __ldg(&erow[j + 2]) : 0.f;
            v.w = ((unsigned)(j + 3 - i) <= BAND) ? sv * __ldg(&erow[j + 3]) : 0.f;
            __stcs(&orow[c4], v);   // same thread as the zero store -> ordered
        }
    }
}

extern "C" void kernel_launch(void* const* d_in, const int* in_sizes, int n_in,
                              void* d_out, int out_size)
{
    const float* s = (const float*)d_in[0];
    const float* e = (const float*)d_in[1];
    float* out = (float*)d_out;

    band_outer_kernel<<<16 * LDIM, 256>>>(s, e, out);
}